// round 1
// baseline (speedup 1.0000x reference)
#include <cuda_runtime.h>
#include <cstdint>

// ---------------------------------------------------------------- problem dims
#define BATCH 2
#define NH    16
#define TQL   2048
#define TPAST 2048
#define TKVL  4096          // TPAST + TQL
#define DKH   64
#define DM    1024
#define MTOK  (BATCH*TQL)   // 4096

// d_out layout: [out (MTOK*DM)] [K (B*H*TKV*DK)] [V (B*H*TKV*DK)]
#define OUT_K_OFF (MTOK*DM)
#define OUT_V_OFF (OUT_K_OFF + BATCH*NH*TKVL*DKH)

// ---------------------------------------------------------------- scratch (no runtime alloc allowed)
__device__ float g_Q[BATCH*NH*TQL*DKH];   // Q in [b][h][t][d] layout
__device__ float g_O[MTOK*DM];            // attention output in [b*TQ + t][D] layout

// ---------------------------------------------------------------- helpers
__device__ __forceinline__ uint32_t f2tf32(float x){
    uint32_t r; asm("cvt.rna.tf32.f32 %0, %1;" : "=r"(r) : "f"(x)); return r;
}
__device__ __forceinline__ float ex2(float x){
    float r; asm("ex2.approx.f32 %0, %1;" : "=f"(r) : "f"(x)); return r;
}
// D = A(16x8) * B(8x8) + D, tf32 inputs, f32 accumulate
__device__ __forceinline__ void mma_tf32(float* c, const uint32_t* a, const uint32_t* b){
    asm volatile("mma.sync.aligned.m16n8k8.row.col.f32.tf32.tf32.f32 "
        "{%0,%1,%2,%3},{%4,%5,%6,%7},{%8,%9},{%0,%1,%2,%3};\n"
        : "+f"(c[0]), "+f"(c[1]), "+f"(c[2]), "+f"(c[3])
        : "r"(a[0]), "r"(a[1]), "r"(a[2]), "r"(a[3]), "r"(b[0]), "r"(b[1]));
}

// ---------------------------------------------------------------- past-KV copy
// past_K/past_V: [B,H,TPAST,DK] contiguous -> rows [0..TPAST) of [B,H,TKV,DK]
__global__ void copy_past(const float4* __restrict__ pk, const float4* __restrict__ pv,
                          float4* __restrict__ dk, float4* __restrict__ dv)
{
    const int per = BATCH*NH*TPAST*DKH/4;  // 1,048,576 float4 per tensor
    int i = blockIdx.x*blockDim.x + threadIdx.x;
    if (i < per){
        int bh  = i / (TPAST*DKH/4);       // / 32768
        int rem = i - bh*(TPAST*DKH/4);
        dk[bh*(TKVL*DKH/4) + rem] = pk[i];
        dv[bh*(TKVL*DKH/4) + rem] = pv[i];
    }
}

// ---------------------------------------------------------------- projection GEMM
// C[M=4096, N=1024] = A[M,1024] @ W[N,1024]^T + bias  (3xTF32 error-compensated)
// MODE 0: A = Ain (query),  write g_Q   at [b][h][t][d]
// MODE 1: A = Ain (key/val),write dst   at [b][h][TPAST+t][d]   (K/V region of d_out)
// MODE 2: A = g_O,          write dst   at [row][n]             (final out)
template<int MODE>
__global__ void __launch_bounds__(256)
proj_gemm(const float* __restrict__ Ain, const float* __restrict__ W,
          const float* __restrict__ bias, float* __restrict__ dst)
{
    __shared__ float As[128*20];   // 128 rows x 16 cols, pad to 20 (conflict-free frag loads)
    __shared__ float Bs[128*20];

    const float* A = (MODE == 2) ? g_O : Ain;
    float* D = (MODE == 0) ? g_Q : dst;

    const int tid  = threadIdx.x;
    const int lane = tid & 31, warp = tid >> 5;
    const int g = lane >> 2, tg = lane & 3;
    const int wm = warp & 3, wn = warp >> 2;          // warps 4 (M) x 2 (N)
    const int m0 = blockIdx.y * 128, n0 = blockIdx.x * 128;
    const int mbase = wm * 32, nbase = wn * 64;       // warp tile 32x64

    float c[2][8][4];
    #pragma unroll
    for (int i = 0; i < 2; i++)
        #pragma unroll
        for (int j = 0; j < 8; j++)
            #pragma unroll
            for (int k = 0; k < 4; k++) c[i][j][k] = 0.f;

    for (int kt = 0; kt < DM/16; kt++){
        const int k0 = kt * 16;
        #pragma unroll
        for (int i = 0; i < 2; i++){
            int idx = tid + i*256;                 // 512 float4 per tile
            int r = idx >> 2, c4 = (idx & 3) << 2;
            *(float4*)&As[r*20 + c4] = *(const float4*)&A[(m0 + r)*DM + k0 + c4];
            *(float4*)&Bs[r*20 + c4] = *(const float4*)&W[(n0 + r)*DM + k0 + c4];
        }
        __syncthreads();
        #pragma unroll
        for (int ks = 0; ks < 2; ks++){
            const int k = ks*8;
            uint32_t ah[2][4], al[2][4];
            #pragma unroll
            for (int fm = 0; fm < 2; fm++){
                const int rr = mbase + fm*16;
                float x0 = As[(rr+g  )*20 + k + tg];
                float x1 = As[(rr+g+8)*20 + k + tg];
                float x2 = As[(rr+g  )*20 + k + tg + 4];
                float x3 = As[(rr+g+8)*20 + k + tg + 4];
                ah[fm][0] = f2tf32(x0); al[fm][0] = f2tf32(x0 - __uint_as_float(ah[fm][0]));
                ah[fm][1] = f2tf32(x1); al[fm][1] = f2tf32(x1 - __uint_as_float(ah[fm][1]));
                ah[fm][2] = f2tf32(x2); al[fm][2] = f2tf32(x2 - __uint_as_float(ah[fm][2]));
                ah[fm][3] = f2tf32(x3); al[fm][3] = f2tf32(x3 - __uint_as_float(ah[fm][3]));
            }
            #pragma unroll
            for (int fn = 0; fn < 8; fn++){
                float y0 = Bs[(nbase+fn*8+g)*20 + k + tg];
                float y1 = Bs[(nbase+fn*8+g)*20 + k + tg + 4];
                uint32_t bh[2], bl[2];
                bh[0] = f2tf32(y0); bl[0] = f2tf32(y0 - __uint_as_float(bh[0]));
                bh[1] = f2tf32(y1); bl[1] = f2tf32(y1 - __uint_as_float(bh[1]));
                #pragma unroll
                for (int fm = 0; fm < 2; fm++){
                    mma_tf32(c[fm][fn], ah[fm], bh);   // hi*hi
                    mma_tf32(c[fm][fn], al[fm], bh);   // lo*hi
                    mma_tf32(c[fm][fn], ah[fm], bl);   // hi*lo
                }
            }
        }
        __syncthreads();
    }

    // epilogue: bias add + scatter (cols 2tg,2tg+1 contiguous -> float2 stores)
    #pragma unroll
    for (int fm = 0; fm < 2; fm++){
        #pragma unroll
        for (int fn = 0; fn < 8; fn++){
            const int n = n0 + nbase + fn*8 + 2*tg;
            const float b0 = bias[n], b1 = bias[n+1];
            #pragma unroll
            for (int half = 0; half < 2; half++){
                const int r  = m0 + mbase + fm*16 + g + half*8;
                const float v0 = c[fm][fn][half*2+0] + b0;
                const float v1 = c[fm][fn][half*2+1] + b1;
                if (MODE == 2){
                    *(float2*)&D[r*DM + n] = make_float2(v0, v1);
                } else {
                    const int bb = r / TQL, t = r - bb*TQL;
                    const int h = n >> 6, d = n & 63;
                    if (MODE == 0)
                        *(float2*)&D[(((bb*NH + h)*TQL  + t        )*DKH) + d] = make_float2(v0, v1);
                    else
                        *(float2*)&D[(((bb*NH + h)*TKVL + TPAST + t)*DKH) + d] = make_float2(v0, v1);
                }
            }
        }
    }
}

// ---------------------------------------------------------------- flash attention
// one block per (b, h, 64-query tile); 4 warps x 16 query rows; KV tiles of 64
__global__ void __launch_bounds__(128)
flash_attn(const float* __restrict__ Kc, const float* __restrict__ Vc)
{
    __shared__ float SK[64*68];   // Q tile first, then K tiles (pad 68: conflict-free)
    __shared__ float SV[64*72];   // V tiles (pad 72: conflict-free for k-major frag reads)

    const int tid = threadIdx.x, lane = tid & 31, warp = tid >> 5;
    const int g = lane >> 2, tg = lane & 3;
    const int qt = blockIdx.x, h = blockIdx.y, b = blockIdx.z;
    const int q0 = qt * 64;
    const int bh = b*NH + h;
    const float* Qp = g_Q + bh*TQL*DKH + q0*DKH;
    const float* Kp = Kc + bh*TKVL*DKH;
    const float* Vp = Vc + bh*TKVL*DKH;

    // load Q tile (64x64) into SK
    #pragma unroll
    for (int i = 0; i < 8; i++){
        int idx = tid + i*128;             // 1024 float4
        int r = idx >> 4, c4 = (idx & 15) << 2;
        *(float4*)&SK[r*68 + c4] = *(const float4*)&Qp[r*64 + c4];
    }
    __syncthreads();

    // preload Q fragments into registers; fold 1/sqrt(dk) * log2(e) so softmax is pure exp2
    const float qscale = 0.125f * 1.44269504088896341f;
    uint32_t aq[8][4];
    const int wrow = warp*16;
    #pragma unroll
    for (int ks = 0; ks < 8; ks++){
        const int k = ks*8;
        aq[ks][0] = f2tf32(SK[(wrow+g  )*68 + k + tg    ] * qscale);
        aq[ks][1] = f2tf32(SK[(wrow+g+8)*68 + k + tg    ] * qscale);
        aq[ks][2] = f2tf32(SK[(wrow+g  )*68 + k + tg + 4] * qscale);
        aq[ks][3] = f2tf32(SK[(wrow+g+8)*68 + k + tg + 4] * qscale);
    }
    __syncthreads();   // done reading Q from SK; K tiles will overwrite it

    float m_i[2] = {-1e30f, -1e30f};
    float l_i[2] = {0.f, 0.f};
    float o[8][4];
    #pragma unroll
    for (int fn = 0; fn < 8; fn++)
        #pragma unroll
        for (int k = 0; k < 4; k++) o[fn][k] = 0.f;

    const int jlimit = TPAST/64 + qt;      // index of the (single) diagonal tile

    for (int jt = 0; jt <= jlimit; jt++){
        const float* Kt = Kp + jt*64*DKH;
        const float* Vt = Vp + jt*64*DKH;
        #pragma unroll
        for (int i = 0; i < 8; i++){
            int idx = tid + i*128;
            int r = idx >> 4, c4 = (idx & 15) << 2;
            *(float4*)&SK[r*68 + c4] = *(const float4*)&Kt[r*64 + c4];
            *(float4*)&SV[r*72 + c4] = *(const float4*)&Vt[r*64 + c4];
        }
        __syncthreads();

        // S = (Q*scale) @ K^T   (warp rows wrow..wrow+15, all 64 kv cols)
        float s[8][4];
        #pragma unroll
        for (int fn = 0; fn < 8; fn++)
            #pragma unroll
            for (int k = 0; k < 4; k++) s[fn][k] = 0.f;
        #pragma unroll
        for (int ks = 0; ks < 8; ks++){
            const int k = ks*8;
            #pragma unroll
            for (int fn = 0; fn < 8; fn++){
                uint32_t bf[2];
                bf[0] = f2tf32(SK[(fn*8+g)*68 + k + tg    ]);
                bf[1] = f2tf32(SK[(fn*8+g)*68 + k + tg + 4]);
                mma_tf32(s[fn], aq[ks], bf);
            }
        }

        // causal mask on the diagonal tile: local col must be <= local row
        if (jt == jlimit){
            #pragma unroll
            for (int fn = 0; fn < 8; fn++){
                const int c0 = fn*8 + 2*tg;
                const int r0 = wrow + g;
                if (c0     > r0    ) s[fn][0] = -1e30f;
                if (c0 + 1 > r0    ) s[fn][1] = -1e30f;
                if (c0     > r0 + 8) s[fn][2] = -1e30f;
                if (c0 + 1 > r0 + 8) s[fn][3] = -1e30f;
            }
        }

        // online softmax (exp2 domain)
        float mx0 = -1e30f, mx1 = -1e30f;
        #pragma unroll
        for (int fn = 0; fn < 8; fn++){
            mx0 = fmaxf(mx0, fmaxf(s[fn][0], s[fn][1]));
            mx1 = fmaxf(mx1, fmaxf(s[fn][2], s[fn][3]));
        }
        mx0 = fmaxf(mx0, __shfl_xor_sync(0xffffffffu, mx0, 1));
        mx0 = fmaxf(mx0, __shfl_xor_sync(0xffffffffu, mx0, 2));
        mx1 = fmaxf(mx1, __shfl_xor_sync(0xffffffffu, mx1, 1));
        mx1 = fmaxf(mx1, __shfl_xor_sync(0xffffffffu, mx1, 2));
        const float mn0 = fmaxf(m_i[0], mx0);
        const float mn1 = fmaxf(m_i[1], mx1);
        const float f0 = ex2(m_i[0] - mn0);
        const float f1 = ex2(m_i[1] - mn1);
        m_i[0] = mn0; m_i[1] = mn1;

        float rs0 = 0.f, rs1 = 0.f;
        #pragma unroll
        for (int fn = 0; fn < 8; fn++){
            s[fn][0] = ex2(s[fn][0] - mn0);
            s[fn][1] = ex2(s[fn][1] - mn0);
            s[fn][2] = ex2(s[fn][2] - mn1);
            s[fn][3] = ex2(s[fn][3] - mn1);
            rs0 += s[fn][0] + s[fn][1];
            rs1 += s[fn][2] + s[fn][3];
        }
        rs0 += __shfl_xor_sync(0xffffffffu, rs0, 1);
        rs0 += __shfl_xor_sync(0xffffffffu, rs0, 2);
        rs1 += __shfl_xor_sync(0xffffffffu, rs1, 1);
        rs1 += __shfl_xor_sync(0xffffffffu, rs1, 2);
        l_i[0] = l_i[0]*f0 + rs0;
        l_i[1] = l_i[1]*f1 + rs1;
        #pragma unroll
        for (int fn = 0; fn < 8; fn++){
            o[fn][0] *= f0; o[fn][1] *= f0;
            o[fn][2] *= f1; o[fn][3] *= f1;
        }

        // O += P @ V : relayout P (C-frag) -> A-frag via shuffles, then mma
        const int src0 = (lane & ~3) | (tg >> 1);
        const int src1 = src0 + 2;
        const bool odd = (tg & 1);
        #pragma unroll
        for (int ks = 0; ks < 8; ks++){
            float v00 = __shfl_sync(0xffffffffu, s[ks][0], src0);
            float v01 = __shfl_sync(0xffffffffu, s[ks][1], src0);
            float v02 = __shfl_sync(0xffffffffu, s[ks][2], src0);
            float v03 = __shfl_sync(0xffffffffu, s[ks][3], src0);
            float v10 = __shfl_sync(0xffffffffu, s[ks][0], src1);
            float v11 = __shfl_sync(0xffffffffu, s[ks][1], src1);
            float v12 = __shfl_sync(0xffffffffu, s[ks][2], src1);
            float v13 = __shfl_sync(0xffffffffu, s[ks][3], src1);
            uint32_t ap[4];
            ap[0] = f2tf32(odd ? v01 : v00);
            ap[1] = f2tf32(odd ? v03 : v02);
            ap[2] = f2tf32(odd ? v11 : v10);
            ap[3] = f2tf32(odd ? v13 : v12);
            const int k = ks*8;
            #pragma unroll
            for (int fn = 0; fn < 8; fn++){
                uint32_t bf[2];
                bf[0] = f2tf32(SV[(k+tg  )*72 + fn*8 + g]);
                bf[1] = f2tf32(SV[(k+tg+4)*72 + fn*8 + g]);
                mma_tf32(o[fn], ap, bf);
            }
        }
        __syncthreads();   // all warps done with SK/SV before next tile load
    }

    // normalize + write to g_O at [b*TQ + t][h*64 + d]
    const float inv0 = 1.f / l_i[0];
    const float inv1 = 1.f / l_i[1];
    float* Op = g_O + (b*TQL + q0)*DM + h*DKH;
    #pragma unroll
    for (int fn = 0; fn < 8; fn++){
        const int cc = fn*8 + 2*tg;
        *(float2*)&Op[(wrow+g  )*DM + cc] = make_float2(o[fn][0]*inv0, o[fn][1]*inv0);
        *(float2*)&Op[(wrow+g+8)*DM + cc] = make_float2(o[fn][2]*inv1, o[fn][3]*inv1);
    }
}

// ---------------------------------------------------------------- launch
extern "C" void kernel_launch(void* const* d_in, const int* in_sizes, int n_in,
                              void* d_out, int out_size)
{
    (void)in_sizes; (void)n_in; (void)out_size;
    const float* query = (const float*)d_in[0];
    const float* key   = (const float*)d_in[1];
    const float* value = (const float*)d_in[2];
    const float* pastK = (const float*)d_in[3];
    const float* pastV = (const float*)d_in[4];
    /* d_in[5] = mask: causal structure computed analytically */
    const float* Wq = (const float*)d_in[6];
    const float* bq = (const float*)d_in[7];
    const float* Wk = (const float*)d_in[8];
    const float* bk = (const float*)d_in[9];
    const float* Wv = (const float*)d_in[10];
    const float* bv = (const float*)d_in[11];
    const float* Wo = (const float*)d_in[12];
    const float* bo = (const float*)d_in[13];

    float* out  = (float*)d_out;
    float* Kout = out + OUT_K_OFF;
    float* Vout = out + OUT_V_OFF;

    // 1. copy past KV into output cache rows [0..TPAST)
    {
        const int per = BATCH*NH*TPAST*DKH/4;
        copy_past<<<per/256, 256>>>((const float4*)pastK, (const float4*)pastV,
                                    (float4*)Kout, (float4*)Vout);
    }

    // 2-4. projections (3xTF32)
    dim3 gdim(DM/128, MTOK/128);   // (8, 32)
    proj_gemm<0><<<gdim, 256>>>(query, Wq, bq, nullptr);   // Q -> g_Q
    proj_gemm<1><<<gdim, 256>>>(key,   Wk, bk, Kout);      // K -> d_out rows [TPAST..TKV)
    proj_gemm<1><<<gdim, 256>>>(value, Wv, bv, Vout);      // V -> d_out rows [TPAST..TKV)

    // 5. causal flash attention -> g_O
    dim3 adim(TQL/64, NH, BATCH);  // (32, 16, 2)
    flash_attn<<<adim, 128>>>(Kout, Vout);

    // 6. output projection (3xTF32) -> d_out[0 .. MTOK*DM)
    proj_gemm<2><<<gdim, 256>>>(nullptr, Wo, bo, out);
}

// round 2
// speedup vs baseline: 1.2801x; 1.2801x over previous
#include <cuda_runtime.h>
#include <cstdint>

// ---------------------------------------------------------------- problem dims
#define BATCH 2
#define NH    16
#define TQL   2048
#define TPAST 2048
#define TKVL  4096          // TPAST + TQL
#define DKH   64
#define DM    1024
#define MTOK  (BATCH*TQL)   // 4096

// d_out layout: [out (MTOK*DM)] [K (B*H*TKV*DK)] [V (B*H*TKV*DK)]
#define OUT_K_OFF (MTOK*DM)
#define OUT_V_OFF (OUT_K_OFF + BATCH*NH*TKVL*DKH)

// proj smem geometry (words)
#define PROW    20              // padded row stride (words) -> conflict-free frags
#define HALF_W  (128*PROW)      // one 128x16 tile buffer = 2560 words
#define STAGE3_W (4*HALF_W)     // Ahi,Bhi,Alo,Blo = 10240 words
#define STAGE1_W (2*HALF_W)     // Ahi,Bhi          = 5120 words

// ---------------------------------------------------------------- scratch
__device__ float g_Q[BATCH*NH*TQL*DKH];   // Q in [b][h][t][d]
__device__ float g_O[MTOK*DM];            // attention out in [b*TQ+t][D]

// ---------------------------------------------------------------- helpers
__device__ __forceinline__ uint32_t f2tf32(float x){
    uint32_t r; asm("cvt.rna.tf32.f32 %0, %1;" : "=r"(r) : "f"(x)); return r;
}
__device__ __forceinline__ float ex2(float x){
    float r; asm("ex2.approx.f32 %0, %1;" : "=f"(r) : "f"(x)); return r;
}
__device__ __forceinline__ void mma_tf32(float* c, const uint32_t* a, const uint32_t* b){
    asm volatile("mma.sync.aligned.m16n8k8.row.col.f32.tf32.tf32.f32 "
        "{%0,%1,%2,%3},{%4,%5,%6,%7},{%8,%9},{%0,%1,%2,%3};\n"
        : "+f"(c[0]), "+f"(c[1]), "+f"(c[2]), "+f"(c[3])
        : "r"(a[0]), "r"(a[1]), "r"(a[2]), "r"(a[3]), "r"(b[0]), "r"(b[1]));
}

// store one float4 as tf32 hi (and optional lo residual) bit patterns
template<bool LO>
__device__ __forceinline__ void stash4(uint32_t* hi, uint32_t* lo, float4 v){
    uint4 h;
    h.x = f2tf32(v.x); h.y = f2tf32(v.y); h.z = f2tf32(v.z); h.w = f2tf32(v.w);
    *(uint4*)hi = h;
    if (LO){
        uint4 l;
        l.x = f2tf32(v.x - __uint_as_float(h.x));
        l.y = f2tf32(v.y - __uint_as_float(h.y));
        l.z = f2tf32(v.z - __uint_as_float(h.z));
        l.w = f2tf32(v.w - __uint_as_float(h.w));
        *(uint4*)lo = l;
    }
}

// ---------------------------------------------------------------- past-KV copy
__global__ void copy_past(const float4* __restrict__ pk, const float4* __restrict__ pv,
                          float4* __restrict__ dk, float4* __restrict__ dv)
{
    const int per = BATCH*NH*TPAST*DKH/4;  // 1,048,576 float4 per tensor
    int i = blockIdx.x*blockDim.x + threadIdx.x;
    if (i < per){
        int bh  = i / (TPAST*DKH/4);
        int rem = i - bh*(TPAST*DKH/4);
        dk[bh*(TKVL*DKH/4) + rem] = pk[i];
        dv[bh*(TKVL*DKH/4) + rem] = pv[i];
    }
}

// ---------------------------------------------------------------- projection GEMM body
// C[4096,1024] = A @ W^T + bias; tf32, SPLIT=3 -> error-compensated (hi/lo)
// MODE 0: A=Ain, D=g_Q  [b][h][t][d];  MODE 1: A=Ain, D=dst KV-cache rows [TPAST..)
// MODE 2: A=g_O, D=dst row-major.
// 2-stage smem pipeline with register prefetch; smem holds PRE-CONVERTED tf32 bits.
template<int SPLIT, int MODE>
__device__ __forceinline__ void proj_body(const float* __restrict__ Ain,
                                          const float* __restrict__ W,
                                          const float* __restrict__ bias,
                                          float* __restrict__ dst)
{
    extern __shared__ uint32_t sm[];
    const int STAGE_W = (SPLIT==3) ? STAGE3_W : STAGE1_W;
    const float* A = (MODE==2) ? g_O : Ain;
    float* D = (MODE==0) ? g_Q : dst;

    const int tid  = threadIdx.x;
    const int lane = tid & 31, warp = tid >> 5;
    const int g = lane >> 2, tg = lane & 3;
    const int wm = warp & 3, wn = warp >> 2;          // 4 (M) x 2 (N)
    const int m0 = blockIdx.y * 128, n0 = blockIdx.x * 128;
    const int mbase = wm * 32, nbase = wn * 64;       // warp tile 32x64

    const int r0  = tid >> 2;          // 0..63
    const int c40 = (tid & 3) << 2;    // 0,4,8,12

    const float* Arow0 = &A[(m0 + r0     )*DM + c40];
    const float* Arow1 = &A[(m0 + r0 + 64)*DM + c40];
    const float* Brow0 = &W[(n0 + r0     )*DM + c40];
    const float* Brow1 = &W[(n0 + r0 + 64)*DM + c40];

    float c[2][8][4];
    #pragma unroll
    for (int i = 0; i < 2; i++)
        #pragma unroll
        for (int j = 0; j < 8; j++)
            #pragma unroll
            for (int k = 0; k < 4; k++) c[i][j][k] = 0.f;

    auto sts = [&](int s, float4 a0, float4 a1, float4 b0, float4 b1){
        uint32_t* H = sm + s*STAGE_W;
        uint32_t* A_hi0 = H + r0*PROW + c40;
        uint32_t* A_hi1 = H + (r0+64)*PROW + c40;
        uint32_t* B_hi0 = H + HALF_W + r0*PROW + c40;
        uint32_t* B_hi1 = H + HALF_W + (r0+64)*PROW + c40;
        stash4<SPLIT==3>(A_hi0, A_hi0 + 2*HALF_W, a0);
        stash4<SPLIT==3>(A_hi1, A_hi1 + 2*HALF_W, a1);
        stash4<SPLIT==3>(B_hi0, B_hi0 + 2*HALF_W, b0);
        stash4<SPLIT==3>(B_hi1, B_hi1 + 2*HALF_W, b1);
    };

    auto compute = [&](int s){
        const uint32_t* H = sm + s*STAGE_W;
        #pragma unroll
        for (int ks = 0; ks < 2; ks++){
            const int k = ks*8;
            uint32_t ah[2][4], al[2][4];
            #pragma unroll
            for (int fm = 0; fm < 2; fm++){
                const uint32_t* base = H + (mbase + fm*16)*PROW + k + tg;
                ah[fm][0] = base[ g   *PROW    ];
                ah[fm][1] = base[(g+8)*PROW    ];
                ah[fm][2] = base[ g   *PROW + 4];
                ah[fm][3] = base[(g+8)*PROW + 4];
                if (SPLIT == 3){
                    const uint32_t* lb = base + 2*HALF_W;
                    al[fm][0] = lb[ g   *PROW    ];
                    al[fm][1] = lb[(g+8)*PROW    ];
                    al[fm][2] = lb[ g   *PROW + 4];
                    al[fm][3] = lb[(g+8)*PROW + 4];
                }
            }
            #pragma unroll
            for (int fn = 0; fn < 8; fn++){
                const uint32_t* bb = H + HALF_W + (nbase + fn*8 + g)*PROW + k + tg;
                uint32_t bh[2] = { bb[0], bb[4] };
                mma_tf32(c[0][fn], ah[0], bh);
                mma_tf32(c[1][fn], ah[1], bh);
                if (SPLIT == 3){
                    uint32_t bl[2] = { bb[2*HALF_W], bb[2*HALF_W + 4] };
                    mma_tf32(c[0][fn], al[0], bh);
                    mma_tf32(c[1][fn], al[1], bh);
                    mma_tf32(c[0][fn], ah[0], bl);
                    mma_tf32(c[1][fn], ah[1], bl);
                }
            }
        }
    };

    // prologue: tile 0
    {
        float4 a0 = *(const float4*)(Arow0);
        float4 a1 = *(const float4*)(Arow1);
        float4 b0 = *(const float4*)(Brow0);
        float4 b1 = *(const float4*)(Brow1);
        sts(0, a0, a1, b0, b1);
    }
    __syncthreads();

    #pragma unroll 1
    for (int kt = 0; kt < DM/16; kt++){
        float4 na0, na1, nb0, nb1;
        const bool more = (kt + 1 < DM/16);
        if (more){
            const int off = (kt+1)*16;
            na0 = *(const float4*)(Arow0 + off);
            na1 = *(const float4*)(Arow1 + off);
            nb0 = *(const float4*)(Brow0 + off);
            nb1 = *(const float4*)(Brow1 + off);
        }
        compute(kt & 1);
        if (more) sts((kt+1) & 1, na0, na1, nb0, nb1);
        __syncthreads();
    }

    // epilogue: bias + scatter
    #pragma unroll
    for (int fm = 0; fm < 2; fm++){
        #pragma unroll
        for (int fn = 0; fn < 8; fn++){
            const int n = n0 + nbase + fn*8 + 2*tg;
            const float b0 = bias[n], b1 = bias[n+1];
            #pragma unroll
            for (int half = 0; half < 2; half++){
                const int r  = m0 + mbase + fm*16 + g + half*8;
                const float v0 = c[fm][fn][half*2+0] + b0;
                const float v1 = c[fm][fn][half*2+1] + b1;
                if (MODE == 2){
                    *(float2*)&D[r*DM + n] = make_float2(v0, v1);
                } else {
                    const int bb = r / TQL, t = r - bb*TQL;
                    const int h = n >> 6, d = n & 63;
                    if (MODE == 0)
                        *(float2*)&D[(((bb*NH + h)*TQL  + t        )*DKH) + d] = make_float2(v0, v1);
                    else
                        *(float2*)&D[(((bb*NH + h)*TKVL + TPAST + t)*DKH) + d] = make_float2(v0, v1);
                }
            }
        }
    }
}

// fused Q/K/V projections: z=0 -> Q (plain tf32), z=1 -> K, z=2 -> V (3xTF32)
__global__ void __launch_bounds__(256,2)
proj_qkv(const float* __restrict__ q, const float* __restrict__ k, const float* __restrict__ v,
         const float* __restrict__ Wq, const float* __restrict__ Wk, const float* __restrict__ Wv,
         const float* __restrict__ bq, const float* __restrict__ bk, const float* __restrict__ bv,
         float* __restrict__ Kout, float* __restrict__ Vout)
{
    if      (blockIdx.z == 0) proj_body<1,0>(q, Wq, bq, nullptr);
    else if (blockIdx.z == 1) proj_body<3,1>(k, Wk, bk, Kout);
    else                      proj_body<3,1>(v, Wv, bv, Vout);
}

// output projection: plain tf32
__global__ void __launch_bounds__(256,2)
proj_out(const float* __restrict__ Wo, const float* __restrict__ bo, float* __restrict__ out)
{
    proj_body<1,2>(nullptr, Wo, bo, out);
}

// ---------------------------------------------------------------- flash attention
// one block per (b, h, 64-query tile); 4 warps x 16 q rows; KV tiles of 64.
// K/V tiles are PRE-CONVERTED to tf32 bit patterns at smem-store time.
__global__ void __launch_bounds__(128,4)
flash_attn(const float* __restrict__ Kc, const float* __restrict__ Vc)
{
    __shared__ uint32_t SK[64*68];
    __shared__ uint32_t SV[64*72];

    const int tid = threadIdx.x, lane = tid & 31, warp = tid >> 5;
    const int g = lane >> 2, tg = lane & 3;
    const int qt = blockIdx.x, h = blockIdx.y, b = blockIdx.z;
    const int q0 = qt * 64;
    const int bh = b*NH + h;
    const float* Qp = g_Q + bh*TQL*DKH + q0*DKH;
    const float* Kp = Kc + bh*TKVL*DKH;
    const float* Vp = Vc + bh*TKVL*DKH;

    // load Q tile (raw float bits) into SK
    #pragma unroll
    for (int i = 0; i < 8; i++){
        int idx = tid + i*128;
        int r = idx >> 4, c4 = (idx & 15) << 2;
        *(uint4*)&SK[r*68 + c4] = *(const uint4*)&Qp[r*64 + c4];
    }
    __syncthreads();

    const float qscale = 0.125f * 1.44269504088896341f;   // 1/sqrt(64) * log2(e)
    uint32_t aq[8][4];
    const int wrow = warp*16;
    #pragma unroll
    for (int ks = 0; ks < 8; ks++){
        const int k = ks*8;
        aq[ks][0] = f2tf32(__uint_as_float(SK[(wrow+g  )*68 + k + tg    ]) * qscale);
        aq[ks][1] = f2tf32(__uint_as_float(SK[(wrow+g+8)*68 + k + tg    ]) * qscale);
        aq[ks][2] = f2tf32(__uint_as_float(SK[(wrow+g  )*68 + k + tg + 4]) * qscale);
        aq[ks][3] = f2tf32(__uint_as_float(SK[(wrow+g+8)*68 + k + tg + 4]) * qscale);
    }
    __syncthreads();

    float m_i[2] = {-1e30f, -1e30f};
    float l_i[2] = {0.f, 0.f};
    float o[8][4];
    #pragma unroll
    for (int fn = 0; fn < 8; fn++)
        #pragma unroll
        for (int k = 0; k < 4; k++) o[fn][k] = 0.f;

    const int jlimit = TPAST/64 + qt;

    for (int jt = 0; jt <= jlimit; jt++){
        const float* Kt = Kp + jt*64*DKH;
        const float* Vt = Vp + jt*64*DKH;
        #pragma unroll
        for (int i = 0; i < 8; i++){
            int idx = tid + i*128;
            int r = idx >> 4, c4 = (idx & 15) << 2;
            float4 kf = *(const float4*)&Kt[r*64 + c4];
            float4 vf = *(const float4*)&Vt[r*64 + c4];
            uint4 ku; ku.x=f2tf32(kf.x); ku.y=f2tf32(kf.y); ku.z=f2tf32(kf.z); ku.w=f2tf32(kf.w);
            uint4 vu; vu.x=f2tf32(vf.x); vu.y=f2tf32(vf.y); vu.z=f2tf32(vf.z); vu.w=f2tf32(vf.w);
            *(uint4*)&SK[r*68 + c4] = ku;
            *(uint4*)&SV[r*72 + c4] = vu;
        }
        __syncthreads();

        // S = (Q*scale) @ K^T
        float s[8][4];
        #pragma unroll
        for (int fn = 0; fn < 8; fn++)
            #pragma unroll
            for (int k = 0; k < 4; k++) s[fn][k] = 0.f;
        #pragma unroll
        for (int ks = 0; ks < 8; ks++){
            const int k = ks*8;
            #pragma unroll
            for (int fn = 0; fn < 8; fn++){
                uint32_t bf[2];
                bf[0] = SK[(fn*8+g)*68 + k + tg    ];
                bf[1] = SK[(fn*8+g)*68 + k + tg + 4];
                mma_tf32(s[fn], aq[ks], bf);
            }
        }

        // causal mask on the diagonal tile
        if (jt == jlimit){
            #pragma unroll
            for (int fn = 0; fn < 8; fn++){
                const int c0 = fn*8 + 2*tg;
                const int r0 = wrow + g;
                if (c0     > r0    ) s[fn][0] = -1e30f;
                if (c0 + 1 > r0    ) s[fn][1] = -1e30f;
                if (c0     > r0 + 8) s[fn][2] = -1e30f;
                if (c0 + 1 > r0 + 8) s[fn][3] = -1e30f;
            }
        }

        // online softmax (exp2 domain)
        float mx0 = -1e30f, mx1 = -1e30f;
        #pragma unroll
        for (int fn = 0; fn < 8; fn++){
            mx0 = fmaxf(mx0, fmaxf(s[fn][0], s[fn][1]));
            mx1 = fmaxf(mx1, fmaxf(s[fn][2], s[fn][3]));
        }
        mx0 = fmaxf(mx0, __shfl_xor_sync(0xffffffffu, mx0, 1));
        mx0 = fmaxf(mx0, __shfl_xor_sync(0xffffffffu, mx0, 2));
        mx1 = fmaxf(mx1, __shfl_xor_sync(0xffffffffu, mx1, 1));
        mx1 = fmaxf(mx1, __shfl_xor_sync(0xffffffffu, mx1, 2));
        const float mn0 = fmaxf(m_i[0], mx0);
        const float mn1 = fmaxf(m_i[1], mx1);
        const float f0 = ex2(m_i[0] - mn0);
        const float f1 = ex2(m_i[1] - mn1);
        m_i[0] = mn0; m_i[1] = mn1;

        float rs0 = 0.f, rs1 = 0.f;
        #pragma unroll
        for (int fn = 0; fn < 8; fn++){
            s[fn][0] = ex2(s[fn][0] - mn0);
            s[fn][1] = ex2(s[fn][1] - mn0);
            s[fn][2] = ex2(s[fn][2] - mn1);
            s[fn][3] = ex2(s[fn][3] - mn1);
            rs0 += s[fn][0] + s[fn][1];
            rs1 += s[fn][2] + s[fn][3];
        }
        rs0 += __shfl_xor_sync(0xffffffffu, rs0, 1);
        rs0 += __shfl_xor_sync(0xffffffffu, rs0, 2);
        rs1 += __shfl_xor_sync(0xffffffffu, rs1, 1);
        rs1 += __shfl_xor_sync(0xffffffffu, rs1, 2);
        l_i[0] = l_i[0]*f0 + rs0;
        l_i[1] = l_i[1]*f1 + rs1;
        #pragma unroll
        for (int fn = 0; fn < 8; fn++){
            o[fn][0] *= f0; o[fn][1] *= f0;
            o[fn][2] *= f1; o[fn][3] *= f1;
        }

        // O += P @ V : C-frag -> A-frag relayout via shuffles
        const int src0 = (lane & ~3) | (tg >> 1);
        const int src1 = src0 + 2;
        const bool odd = (tg & 1);
        #pragma unroll
        for (int ks = 0; ks < 8; ks++){
            float v00 = __shfl_sync(0xffffffffu, s[ks][0], src0);
            float v01 = __shfl_sync(0xffffffffu, s[ks][1], src0);
            float v02 = __shfl_sync(0xffffffffu, s[ks][2], src0);
            float v03 = __shfl_sync(0xffffffffu, s[ks][3], src0);
            float v10 = __shfl_sync(0xffffffffu, s[ks][0], src1);
            float v11 = __shfl_sync(0xffffffffu, s[ks][1], src1);
            float v12 = __shfl_sync(0xffffffffu, s[ks][2], src1);
            float v13 = __shfl_sync(0xffffffffu, s[ks][3], src1);
            uint32_t ap[4];
            ap[0] = f2tf32(odd ? v01 : v00);
            ap[1] = f2tf32(odd ? v03 : v02);
            ap[2] = f2tf32(odd ? v11 : v10);
            ap[3] = f2tf32(odd ? v13 : v12);
            const int k = ks*8;
            #pragma unroll
            for (int fn = 0; fn < 8; fn++){
                uint32_t bf[2];
                bf[0] = SV[(k+tg  )*72 + fn*8 + g];
                bf[1] = SV[(k+tg+4)*72 + fn*8 + g];
                mma_tf32(o[fn], ap, bf);
            }
        }
        __syncthreads();
    }

    // normalize + write g_O at [b*TQ + t][h*64 + d]
    const float inv0 = 1.f / l_i[0];
    const float inv1 = 1.f / l_i[1];
    float* Op = g_O + (b*TQL + q0)*DM + h*DKH;
    #pragma unroll
    for (int fn = 0; fn < 8; fn++){
        const int cc = fn*8 + 2*tg;
        *(float2*)&Op[(wrow+g  )*DM + cc] = make_float2(o[fn][0]*inv0, o[fn][1]*inv0);
        *(float2*)&Op[(wrow+g+8)*DM + cc] = make_float2(o[fn][2]*inv1, o[fn][3]*inv1);
    }
}

// ---------------------------------------------------------------- launch
extern "C" void kernel_launch(void* const* d_in, const int* in_sizes, int n_in,
                              void* d_out, int out_size)
{
    (void)in_sizes; (void)n_in; (void)out_size;
    const float* query = (const float*)d_in[0];
    const float* key   = (const float*)d_in[1];
    const float* value = (const float*)d_in[2];
    const float* pastK = (const float*)d_in[3];
    const float* pastV = (const float*)d_in[4];
    /* d_in[5] = mask: causal structure computed analytically */
    const float* Wq = (const float*)d_in[6];
    const float* bq = (const float*)d_in[7];
    const float* Wk = (const float*)d_in[8];
    const float* bk = (const float*)d_in[9];
    const float* Wv = (const float*)d_in[10];
    const float* bv = (const float*)d_in[11];
    const float* Wo = (const float*)d_in[12];
    const float* bo = (const float*)d_in[13];

    float* out  = (float*)d_out;
    float* Kout = out + OUT_K_OFF;
    float* Vout = out + OUT_V_OFF;

    const int smem_qkv = STAGE3_W * 2 * 4;   // 80 KB
    const int smem_out = STAGE1_W * 2 * 4;   // 40 KB
    cudaFuncSetAttribute(proj_qkv, cudaFuncAttributeMaxDynamicSharedMemorySize, smem_qkv);
    cudaFuncSetAttribute(proj_out, cudaFuncAttributeMaxDynamicSharedMemorySize, smem_out);

    // 1. past KV -> cache rows [0..TPAST)
    {
        const int per = BATCH*NH*TPAST*DKH/4;
        copy_past<<<per/256, 256>>>((const float4*)pastK, (const float4*)pastV,
                                    (float4*)Kout, (float4*)Vout);
    }

    // 2. fused Q/K/V projections
    proj_qkv<<<dim3(DM/128, MTOK/128, 3), 256, smem_qkv>>>(
        query, key, value, Wq, Wk, Wv, bq, bk, bv, Kout, Vout);

    // 3. causal flash attention -> g_O
    flash_attn<<<dim3(TQL/64, NH, BATCH), 128>>>(Kout, Vout);

    // 4. output projection -> d_out[0 .. MTOK*DM)
    proj_out<<<dim3(DM/128, MTOK/128, 1), 256, smem_out>>>(Wo, bo, out);
}

// round 3
// speedup vs baseline: 1.4368x; 1.1224x over previous
#include <cuda_runtime.h>
#include <cstdint>

// ---------------------------------------------------------------- problem dims
#define BATCH 2
#define NH    16
#define TQL   2048
#define TPAST 2048
#define TKVL  4096          // TPAST + TQL
#define DKH   64
#define DM    1024
#define MTOK  (BATCH*TQL)   // 4096

// d_out layout: [out (MTOK*DM)] [K (B*H*TKV*DK)] [V (B*H*TKV*DK)]
#define OUT_K_OFF (MTOK*DM)
#define OUT_V_OFF (OUT_K_OFF + BATCH*NH*TKVL*DKH)

// proj smem geometry (words)
#define PROW    20              // padded row stride -> conflict-free frag loads
#define HALF_W  (128*PROW)      // one 128x16 tile = 2560 words
#define STAGE_W (2*HALF_W)      // A,B = 5120 words
#define PROJ_SMEM_B (STAGE_W*2*4)   // 40960 bytes (2 stages)

// attention smem geometry (words)
#define AK_W 4352               // 64 rows * 68 (pad)  K tile
#define AV_W 4608               // 64 rows * 72 (pad)  V tile
#define ATT_SMEM_W (2*AK_W + 2*AV_W)
#define ATT_SMEM_B (ATT_SMEM_W*4)   // 71680 bytes

// ---------------------------------------------------------------- scratch
__device__ float g_Q[BATCH*NH*TQL*DKH];   // Q in [b][h][t][d]
__device__ float g_O[MTOK*DM];            // attention out in [b*TQ+t][D]

// ---------------------------------------------------------------- helpers
__device__ __forceinline__ uint32_t f2tf32(float x){
    uint32_t r; asm("cvt.rna.tf32.f32 %0, %1;" : "=r"(r) : "f"(x)); return r;
}
__device__ __forceinline__ float ex2(float x){
    float r; asm("ex2.approx.f32 %0, %1;" : "=f"(r) : "f"(x)); return r;
}
__device__ __forceinline__ void mma_tf32(float* c, const uint32_t* a, const uint32_t* b){
    asm volatile("mma.sync.aligned.m16n8k8.row.col.f32.tf32.tf32.f32 "
        "{%0,%1,%2,%3},{%4,%5,%6,%7},{%8,%9},{%0,%1,%2,%3};\n"
        : "+f"(c[0]), "+f"(c[1]), "+f"(c[2]), "+f"(c[3])
        : "r"(a[0]), "r"(a[1]), "r"(a[2]), "r"(a[3]), "r"(b[0]), "r"(b[1]));
}
__device__ __forceinline__ uint32_t s2u(const void* p){
    return (uint32_t)__cvta_generic_to_shared(p);
}
__device__ __forceinline__ void cpa16(uint32_t dst, const void* src){
    asm volatile("cp.async.cg.shared.global [%0], [%1], 16;" :: "r"(dst), "l"(src));
}
__device__ __forceinline__ void cpa_commit(){
    asm volatile("cp.async.commit_group;");
}

// ---------------------------------------------------------------- past-KV copy
__global__ void copy_past(const float4* __restrict__ pk, const float4* __restrict__ pv,
                          float4* __restrict__ dk, float4* __restrict__ dv)
{
    const int per = BATCH*NH*TPAST*DKH/4;
    int i = blockIdx.x*blockDim.x + threadIdx.x;
    if (i < per){
        int bh  = i / (TPAST*DKH/4);
        int rem = i - bh*(TPAST*DKH/4);
        dk[bh*(TKVL*DKH/4) + rem] = pk[i];
        dv[bh*(TKVL*DKH/4) + rem] = pv[i];
    }
}

// ---------------------------------------------------------------- projection GEMM
// C[4096,1024] = A @ W^T + bias, plain TF32 (rna on both operands).
// MODE 0: A=Ain, D=g_Q [b][h][t][d]; MODE 1: A=Ain, D=KV-cache rows [TPAST..)
// MODE 2: A=g_O, D=dst row-major.
template<int MODE>
__device__ __forceinline__ void proj_body(const float* __restrict__ Ain,
                                          const float* __restrict__ W,
                                          const float* __restrict__ bias,
                                          float* __restrict__ dst)
{
    extern __shared__ uint32_t sm[];
    const float* A = (MODE==2) ? g_O : Ain;
    float* D = (MODE==0) ? g_Q : dst;

    const int tid  = threadIdx.x;
    const int lane = tid & 31, warp = tid >> 5;
    const int g = lane >> 2, tg = lane & 3;
    const int wm = warp & 3, wn = warp >> 2;          // 4 (M) x 2 (N)
    const int m0 = blockIdx.y * 128, n0 = blockIdx.x * 128;
    const int mbase = wm * 32, nbase = wn * 64;       // warp tile 32x64

    const int r0  = tid >> 2;
    const int c40 = (tid & 3) << 2;

    const float* Arow0 = &A[(m0 + r0     )*DM + c40];
    const float* Arow1 = &A[(m0 + r0 + 64)*DM + c40];
    const float* Brow0 = &W[(n0 + r0     )*DM + c40];
    const float* Brow1 = &W[(n0 + r0 + 64)*DM + c40];

    float c[2][8][4];
    #pragma unroll
    for (int i = 0; i < 2; i++)
        #pragma unroll
        for (int j = 0; j < 8; j++)
            #pragma unroll
            for (int k = 0; k < 4; k++) c[i][j][k] = 0.f;

    auto cvt4 = [](float4 v){
        uint4 u; u.x=f2tf32(v.x); u.y=f2tf32(v.y); u.z=f2tf32(v.z); u.w=f2tf32(v.w);
        return u;
    };
    auto sts = [&](int s, float4 a0, float4 a1, float4 b0, float4 b1){
        uint32_t* H = sm + s*STAGE_W;
        *(uint4*)(H + r0*PROW + c40)            = cvt4(a0);
        *(uint4*)(H + (r0+64)*PROW + c40)       = cvt4(a1);
        *(uint4*)(H + HALF_W + r0*PROW + c40)   = cvt4(b0);
        *(uint4*)(H + HALF_W + (r0+64)*PROW + c40) = cvt4(b1);
    };

    auto compute = [&](int s){
        const uint32_t* H = sm + s*STAGE_W;
        #pragma unroll
        for (int ks = 0; ks < 2; ks++){
            const int k = ks*8;
            uint32_t ah[2][4];
            #pragma unroll
            for (int fm = 0; fm < 2; fm++){
                const uint32_t* base = H + (mbase + fm*16)*PROW + k + tg;
                ah[fm][0] = base[ g   *PROW    ];
                ah[fm][1] = base[(g+8)*PROW    ];
                ah[fm][2] = base[ g   *PROW + 4];
                ah[fm][3] = base[(g+8)*PROW + 4];
            }
            #pragma unroll
            for (int fn = 0; fn < 8; fn++){
                const uint32_t* bb = H + HALF_W + (nbase + fn*8 + g)*PROW + k + tg;
                uint32_t bh[2] = { bb[0], bb[4] };
                mma_tf32(c[0][fn], ah[0], bh);
                mma_tf32(c[1][fn], ah[1], bh);
            }
        }
    };

    {
        float4 a0 = *(const float4*)(Arow0);
        float4 a1 = *(const float4*)(Arow1);
        float4 b0 = *(const float4*)(Brow0);
        float4 b1 = *(const float4*)(Brow1);
        sts(0, a0, a1, b0, b1);
    }
    __syncthreads();

    #pragma unroll 1
    for (int kt = 0; kt < DM/16; kt++){
        float4 na0, na1, nb0, nb1;
        const bool more = (kt + 1 < DM/16);
        if (more){
            const int off = (kt+1)*16;
            na0 = *(const float4*)(Arow0 + off);
            na1 = *(const float4*)(Arow1 + off);
            nb0 = *(const float4*)(Brow0 + off);
            nb1 = *(const float4*)(Brow1 + off);
        }
        compute(kt & 1);
        if (more) sts((kt+1) & 1, na0, na1, nb0, nb1);
        __syncthreads();
    }

    #pragma unroll
    for (int fm = 0; fm < 2; fm++){
        #pragma unroll
        for (int fn = 0; fn < 8; fn++){
            const int n = n0 + nbase + fn*8 + 2*tg;
            const float b0 = bias[n], b1 = bias[n+1];
            #pragma unroll
            for (int half = 0; half < 2; half++){
                const int r  = m0 + mbase + fm*16 + g + half*8;
                const float v0 = c[fm][fn][half*2+0] + b0;
                const float v1 = c[fm][fn][half*2+1] + b1;
                if (MODE == 2){
                    *(float2*)&D[r*DM + n] = make_float2(v0, v1);
                } else {
                    const int bb = r / TQL, t = r - bb*TQL;
                    const int h = n >> 6, d = n & 63;
                    if (MODE == 0)
                        *(float2*)&D[(((bb*NH + h)*TQL  + t        )*DKH) + d] = make_float2(v0, v1);
                    else
                        *(float2*)&D[(((bb*NH + h)*TKVL + TPAST + t)*DKH) + d] = make_float2(v0, v1);
                }
            }
        }
    }
}

__global__ void __launch_bounds__(256,2)
proj_qkv(const float* __restrict__ q, const float* __restrict__ k, const float* __restrict__ v,
         const float* __restrict__ Wq, const float* __restrict__ Wk, const float* __restrict__ Wv,
         const float* __restrict__ bq, const float* __restrict__ bk, const float* __restrict__ bv,
         float* __restrict__ Kout, float* __restrict__ Vout)
{
    if      (blockIdx.z == 0) proj_body<0>(q, Wq, bq, nullptr);
    else if (blockIdx.z == 1) proj_body<1>(k, Wk, bk, Kout);
    else                      proj_body<1>(v, Wv, bv, Vout);
}

__global__ void __launch_bounds__(256,2)
proj_out(const float* __restrict__ Wo, const float* __restrict__ bo, float* __restrict__ out)
{
    proj_body<2>(nullptr, Wo, bo, out);
}

// ---------------------------------------------------------------- flash attention
// one block per (b, h, 64-query tile); 4 warps x 16 q rows; KV tiles of 64.
// Double-buffered: K via cp.async (raw fp32 bits -> tf32 truncation, benign for
// scores), V via register prefetch + rna convert at STS (unbiased PV).
__global__ void __launch_bounds__(128,3)
flash_attn(const float* __restrict__ Kc, const float* __restrict__ Vc)
{
    extern __shared__ uint32_t dyn[];
    uint32_t* KS[2] = { dyn, dyn + AK_W };
    uint32_t* VS[2] = { dyn + 2*AK_W, dyn + 2*AK_W + AV_W };
    const uint32_t ks_u32[2] = { s2u(KS[0]), s2u(KS[1]) };

    const int tid = threadIdx.x, lane = tid & 31, warp = tid >> 5;
    const int g = lane >> 2, tg = lane & 3;
    const int qt = blockIdx.x, h = blockIdx.y, b = blockIdx.z;
    const int q0 = qt * 64;
    const int bh = b*NH + h;
    const float* Qp = g_Q + bh*TQL*DKH + q0*DKH;
    const float* Kp = Kc + bh*TKVL*DKH;
    const float* Vp = Vc + bh*TKVL*DKH;

    const int rb = tid >> 4;           // row base (0..7), rows rb + 8*i
    const int cc = (tid & 15) << 2;    // col (0..60 step 4)

    // ---- Q staging (into KS[0], overwritten later)
    #pragma unroll
    for (int i = 0; i < 8; i++)
        *(uint4*)&KS[0][(rb+8*i)*68 + cc] = *(const uint4*)&Qp[(rb+8*i)*64 + cc];
    __syncthreads();

    const float qscale = 0.125f * 1.44269504088896341f;   // 1/sqrt(64) * log2(e)
    uint32_t aq[8][4];
    const int wrow = warp*16;
    #pragma unroll
    for (int ks = 0; ks < 8; ks++){
        const int k = ks*8;
        aq[ks][0] = f2tf32(__uint_as_float(KS[0][(wrow+g  )*68 + k + tg    ]) * qscale);
        aq[ks][1] = f2tf32(__uint_as_float(KS[0][(wrow+g+8)*68 + k + tg    ]) * qscale);
        aq[ks][2] = f2tf32(__uint_as_float(KS[0][(wrow+g  )*68 + k + tg + 4]) * qscale);
        aq[ks][3] = f2tf32(__uint_as_float(KS[0][(wrow+g+8)*68 + k + tg + 4]) * qscale);
    }
    __syncthreads();

    float m_i[2] = {-1e30f, -1e30f};
    float l_i[2] = {0.f, 0.f};
    float o[8][4];
    #pragma unroll
    for (int fn = 0; fn < 8; fn++)
        #pragma unroll
        for (int k = 0; k < 4; k++) o[fn][k] = 0.f;

    const int jl = TPAST/64 + qt;      // last (diagonal) tile index

    float4 vr[8];
    auto ldgV = [&](int jt){
        const float* Vt = Vp + jt*64*DKH;
        #pragma unroll
        for (int i = 0; i < 8; i++)
            vr[i] = *(const float4*)&Vt[(rb+8*i)*64 + cc];
    };
    auto fillK = [&](int jt, int st){
        const float* Kt = Kp + jt*64*DKH;
        #pragma unroll
        for (int i = 0; i < 8; i++)
            cpa16(ks_u32[st] + ((rb+8*i)*68 + cc)*4, Kt + (rb+8*i)*64 + cc);
    };
    auto stsV = [&](int st){
        #pragma unroll
        for (int i = 0; i < 8; i++){
            uint4 u; u.x=f2tf32(vr[i].x); u.y=f2tf32(vr[i].y);
                     u.z=f2tf32(vr[i].z); u.w=f2tf32(vr[i].w);
            *(uint4*)&VS[st][(rb+8*i)*72 + cc] = u;
        }
    };

    // prologue: tile 0 in flight
    ldgV(0); fillK(0, 0); cpa_commit();

    #pragma unroll 1
    for (int jt = 0; jt <= jl; jt++){
        const int buf = jt & 1;
        stsV(buf);                      // V(jt) regs -> smem
        if (jt < jl){
            ldgV(jt+1);                 // V(jt+1) -> regs (latency hidden by compute)
            fillK(jt+1, buf^1); cpa_commit();
            asm volatile("cp.async.wait_group 1;");
        } else {
            asm volatile("cp.async.wait_group 0;");
        }
        __syncthreads();                // K(jt) + V(jt) visible to all

        // S = (Q*scale) @ K^T
        float s[8][4];
        #pragma unroll
        for (int fn = 0; fn < 8; fn++)
            #pragma unroll
            for (int k = 0; k < 4; k++) s[fn][k] = 0.f;
        #pragma unroll
        for (int ks = 0; ks < 8; ks++){
            const int k = ks*8;
            #pragma unroll
            for (int fn = 0; fn < 8; fn++){
                uint32_t bf[2];
                bf[0] = KS[buf][(fn*8+g)*68 + k + tg    ];
                bf[1] = KS[buf][(fn*8+g)*68 + k + tg + 4];
                mma_tf32(s[fn], aq[ks], bf);
            }
        }

        // causal mask on the diagonal tile
        if (jt == jl){
            #pragma unroll
            for (int fn = 0; fn < 8; fn++){
                const int c0 = fn*8 + 2*tg;
                const int r0 = wrow + g;
                if (c0     > r0    ) s[fn][0] = -1e30f;
                if (c0 + 1 > r0    ) s[fn][1] = -1e30f;
                if (c0     > r0 + 8) s[fn][2] = -1e30f;
                if (c0 + 1 > r0 + 8) s[fn][3] = -1e30f;
            }
        }

        // online softmax (exp2 domain)
        float mx0 = -1e30f, mx1 = -1e30f;
        #pragma unroll
        for (int fn = 0; fn < 8; fn++){
            mx0 = fmaxf(mx0, fmaxf(s[fn][0], s[fn][1]));
            mx1 = fmaxf(mx1, fmaxf(s[fn][2], s[fn][3]));
        }
        mx0 = fmaxf(mx0, __shfl_xor_sync(0xffffffffu, mx0, 1));
        mx0 = fmaxf(mx0, __shfl_xor_sync(0xffffffffu, mx0, 2));
        mx1 = fmaxf(mx1, __shfl_xor_sync(0xffffffffu, mx1, 1));
        mx1 = fmaxf(mx1, __shfl_xor_sync(0xffffffffu, mx1, 2));
        const float mn0 = fmaxf(m_i[0], mx0);
        const float mn1 = fmaxf(m_i[1], mx1);
        const float f0 = ex2(m_i[0] - mn0);
        const float f1 = ex2(m_i[1] - mn1);
        m_i[0] = mn0; m_i[1] = mn1;

        float rs0 = 0.f, rs1 = 0.f;
        #pragma unroll
        for (int fn = 0; fn < 8; fn++){
            s[fn][0] = ex2(s[fn][0] - mn0);
            s[fn][1] = ex2(s[fn][1] - mn0);
            s[fn][2] = ex2(s[fn][2] - mn1);
            s[fn][3] = ex2(s[fn][3] - mn1);
            rs0 += s[fn][0] + s[fn][1];
            rs1 += s[fn][2] + s[fn][3];
        }
        rs0 += __shfl_xor_sync(0xffffffffu, rs0, 1);
        rs0 += __shfl_xor_sync(0xffffffffu, rs0, 2);
        rs1 += __shfl_xor_sync(0xffffffffu, rs1, 1);
        rs1 += __shfl_xor_sync(0xffffffffu, rs1, 2);
        l_i[0] = l_i[0]*f0 + rs0;
        l_i[1] = l_i[1]*f1 + rs1;
        #pragma unroll
        for (int fn = 0; fn < 8; fn++){
            o[fn][0] *= f0; o[fn][1] *= f0;
            o[fn][2] *= f1; o[fn][3] *= f1;
        }

        // O += P @ V : C-frag -> A-frag relayout via shuffles
        const int src0 = (lane & ~3) | (tg >> 1);
        const int src1 = src0 + 2;
        const bool odd = (tg & 1);
        #pragma unroll
        for (int ks = 0; ks < 8; ks++){
            float v00 = __shfl_sync(0xffffffffu, s[ks][0], src0);
            float v01 = __shfl_sync(0xffffffffu, s[ks][1], src0);
            float v02 = __shfl_sync(0xffffffffu, s[ks][2], src0);
            float v03 = __shfl_sync(0xffffffffu, s[ks][3], src0);
            float v10 = __shfl_sync(0xffffffffu, s[ks][0], src1);
            float v11 = __shfl_sync(0xffffffffu, s[ks][1], src1);
            float v12 = __shfl_sync(0xffffffffu, s[ks][2], src1);
            float v13 = __shfl_sync(0xffffffffu, s[ks][3], src1);
            uint32_t ap[4];
            ap[0] = f2tf32(odd ? v01 : v00);
            ap[1] = f2tf32(odd ? v03 : v02);
            ap[2] = f2tf32(odd ? v11 : v10);
            ap[3] = f2tf32(odd ? v13 : v12);
            const int k = ks*8;
            #pragma unroll
            for (int fn = 0; fn < 8; fn++){
                uint32_t bf[2];
                bf[0] = VS[buf][(k+tg  )*72 + fn*8 + g];
                bf[1] = VS[buf][(k+tg+4)*72 + fn*8 + g];
                mma_tf32(o[fn], ap, bf);
            }
        }
        __syncthreads();   // stage buf free for refill at jt+2
    }

    // normalize + write g_O at [b*TQ + t][h*64 + d]
    const float inv0 = 1.f / l_i[0];
    const float inv1 = 1.f / l_i[1];
    float* Op = g_O + (b*TQL + q0)*DM + h*DKH;
    #pragma unroll
    for (int fn = 0; fn < 8; fn++){
        const int ccc = fn*8 + 2*tg;
        *(float2*)&Op[(wrow+g  )*DM + ccc] = make_float2(o[fn][0]*inv0, o[fn][1]*inv0);
        *(float2*)&Op[(wrow+g+8)*DM + ccc] = make_float2(o[fn][2]*inv1, o[fn][3]*inv1);
    }
}

// ---------------------------------------------------------------- launch
extern "C" void kernel_launch(void* const* d_in, const int* in_sizes, int n_in,
                              void* d_out, int out_size)
{
    (void)in_sizes; (void)n_in; (void)out_size;
    const float* query = (const float*)d_in[0];
    const float* key   = (const float*)d_in[1];
    const float* value = (const float*)d_in[2];
    const float* pastK = (const float*)d_in[3];
    const float* pastV = (const float*)d_in[4];
    /* d_in[5] = mask: causal structure computed analytically */
    const float* Wq = (const float*)d_in[6];
    const float* bq = (const float*)d_in[7];
    const float* Wk = (const float*)d_in[8];
    const float* bk = (const float*)d_in[9];
    const float* Wv = (const float*)d_in[10];
    const float* bv = (const float*)d_in[11];
    const float* Wo = (const float*)d_in[12];
    const float* bo = (const float*)d_in[13];

    float* out  = (float*)d_out;
    float* Kout = out + OUT_K_OFF;
    float* Vout = out + OUT_V_OFF;

    cudaFuncSetAttribute(proj_qkv,  cudaFuncAttributeMaxDynamicSharedMemorySize, PROJ_SMEM_B);
    cudaFuncSetAttribute(proj_out,  cudaFuncAttributeMaxDynamicSharedMemorySize, PROJ_SMEM_B);
    cudaFuncSetAttribute(flash_attn, cudaFuncAttributeMaxDynamicSharedMemorySize, ATT_SMEM_B);

    // 1. past KV -> cache rows [0..TPAST)
    {
        const int per = BATCH*NH*TPAST*DKH/4;
        copy_past<<<per/256, 256>>>((const float4*)pastK, (const float4*)pastV,
                                    (float4*)Kout, (float4*)Vout);
    }

    // 2. fused Q/K/V projections (plain TF32)
    proj_qkv<<<dim3(DM/128, MTOK/128, 3), 256, PROJ_SMEM_B>>>(
        query, key, value, Wq, Wk, Wv, bq, bk, bv, Kout, Vout);

    // 3. causal flash attention -> g_O
    flash_attn<<<dim3(TQL/64, NH, BATCH), 128, ATT_SMEM_B>>>(Kout, Vout);

    // 4. output projection -> d_out[0 .. MTOK*DM)
    proj_out<<<dim3(DM/128, MTOK/128, 1), 256, PROJ_SMEM_B>>>(Wo, bo, out);
}